// round 9
// baseline (speedup 1.0000x reference)
#include <cuda_runtime.h>
#include <cuda_bf16.h>
#include <cstdint>

#define B_ 2
#define L_ 4096
#define H_ 1024

typedef __nv_bfloat16 bf16;

// ---------------- scratch (__device__ globals; no runtime alloc) ------------
__device__ bf16  g_h_hi [B_ * L_ * H_];
__device__ bf16  g_h_lo [B_ * L_ * H_];
__device__ bf16  g_hT_hi[B_ * H_ * L_];
__device__ bf16  g_hT_lo[B_ * H_ * L_];
__device__ bf16  g_WT_hi[H_ * H_];
__device__ bf16  g_WT_lo[H_ * H_];
__device__ bf16  g_G_hi [B_ * H_ * H_];
__device__ bf16  g_G_lo [B_ * H_ * H_];
__device__ bf16  g_MT_hi[B_ * H_ * H_];
__device__ bf16  g_MT_lo[B_ * H_ * H_];
__device__ float g_Gp  [B_ * 2 * H_ * H_];   // split-K fp32 partials for G

// upper-triangle tile LUT: 128-row x 64-col tiles, keep j >= 2i  (72 tiles)
__device__ const int TI_LUT[72] = {
    0,0,0,0,0,0,0,0,0,0,0,0,0,0,0,0,
    1,1,1,1,1,1,1,1,1,1,1,1,1,1,
    2,2,2,2,2,2,2,2,2,2,2,2,
    3,3,3,3,3,3,3,3,3,3,
    4,4,4,4,4,4,4,4,
    5,5,5,5,5,5,
    6,6,6,6,
    7,7};
__device__ const int TJ_LUT[72] = {
    0,1,2,3,4,5,6,7,8,9,10,11,12,13,14,15,
    2,3,4,5,6,7,8,9,10,11,12,13,14,15,
    4,5,6,7,8,9,10,11,12,13,14,15,
    6,7,8,9,10,11,12,13,14,15,
    8,9,10,11,12,13,14,15,
    10,11,12,13,14,15,
    12,13,14,15,
    14,15};

// ---------------- helpers ---------------------------------------------------
__device__ __forceinline__ uint32_t smem_u32(const void* p) {
    uint32_t a;
    asm("{ .reg .u64 t; cvta.to.shared.u64 t, %1; cvt.u32.u64 %0, t; }" : "=r"(a) : "l"(p));
    return a;
}
__device__ __forceinline__ void cp16(uint32_t saddr, const void* gaddr) {
    asm volatile("cp.async.cg.shared.global [%0], [%1], 16;" :: "r"(saddr), "l"(gaddr));
}
__device__ __forceinline__ void cp_commit() {
    asm volatile("cp.async.commit_group;" ::: "memory");
}
__device__ __forceinline__ void cp_wait1() {
    asm volatile("cp.async.wait_group 1;" ::: "memory");
}
__device__ __forceinline__ void ldsm4(uint32_t* r, uint32_t addr) {
    asm volatile("ldmatrix.sync.aligned.m8n8.x4.shared.b16 {%0,%1,%2,%3}, [%4];"
                 : "=r"(r[0]), "=r"(r[1]), "=r"(r[2]), "=r"(r[3]) : "r"(addr));
}
__device__ __forceinline__ void mma16816(float* c, const uint32_t* a, const uint32_t* b) {
    asm volatile(
        "mma.sync.aligned.m16n8k16.row.col.f32.bf16.bf16.f32 "
        "{%0,%1,%2,%3}, {%4,%5,%6,%7}, {%8,%9}, {%0,%1,%2,%3};"
        : "+f"(c[0]), "+f"(c[1]), "+f"(c[2]), "+f"(c[3])
        : "r"(a[0]), "r"(a[1]), "r"(a[2]), "r"(a[3]), "r"(b[0]), "r"(b[1]));
}

// ---------------- fused RoPE + split + transpose ----------------------------
__global__ void rope_split_t(const float* __restrict__ x,
                             const float* __restrict__ cs,
                             const float* __restrict__ sn,
                             bf16* __restrict__ hh, bf16* __restrict__ hl,
                             bf16* __restrict__ hth, bf16* __restrict__ htl) {
    __shared__ bf16 thi[64][66];
    __shared__ bf16 tlo[64][66];
    const int b  = blockIdx.z;
    const int l0 = blockIdx.x * 64;
    const int h0 = blockIdx.y * 64;
    const int tx = threadIdx.x, ty = threadIdx.y;     // 32 x 8
    const long base = (long)b * L_ * H_;
    const int ph0 = (h0 < H_ / 2) ? h0 + H_ / 2 : h0 - H_ / 2;
    const float sgn = (h0 < H_ / 2) ? -1.f : 1.f;
    const int c = 2 * tx;

#pragma unroll
    for (int i = 0; i < 8; i++) {
        int r = ty + 8 * i;
        long l = l0 + r;
        float2 xv = *(const float2*)(x + base + l * H_ + h0 + c);
        float2 pv = *(const float2*)(x + base + l * H_ + ph0 + c);
        float2 cv = *(const float2*)(cs + l * H_ + h0 + c);
        float2 sv = *(const float2*)(sn + l * H_ + h0 + c);
        float o0 = xv.x * cv.x + sgn * pv.x * sv.x;
        float o1 = xv.y * cv.y + sgn * pv.y * sv.y;
        bf16 hi0 = __float2bfloat16_rn(o0);
        bf16 hi1 = __float2bfloat16_rn(o1);
        bf16 lo0 = __float2bfloat16_rn(o0 - __bfloat162float(hi0));
        bf16 lo1 = __float2bfloat16_rn(o1 - __bfloat162float(hi1));
        *(__nv_bfloat162*)(hh + base + l * H_ + h0 + c) = __nv_bfloat162(hi0, hi1);
        *(__nv_bfloat162*)(hl + base + l * H_ + h0 + c) = __nv_bfloat162(lo0, lo1);
        thi[r][c] = hi0; thi[r][c + 1] = hi1;
        tlo[r][c] = lo0; tlo[r][c + 1] = lo1;
    }
    __syncthreads();
#pragma unroll
    for (int i = 0; i < 8; i++) {
        int r = ty + 8 * i;
        long row = h0 + r;
        *(__nv_bfloat162*)(hth + base + row * L_ + l0 + c) =
            __nv_bfloat162(thi[c][r], thi[c + 1][r]);
        *(__nv_bfloat162*)(htl + base + row * L_ + l0 + c) =
            __nv_bfloat162(tlo[c][r], tlo[c + 1][r]);
    }
}

// ---------------- W split + transpose --------------------------------------
__global__ void wsplit_t(const float* __restrict__ W, bf16* __restrict__ wth,
                         bf16* __restrict__ wtl) {
    long e = (long)blockIdx.x * blockDim.x + threadIdx.x;
    int o = (int)(e >> 10), c = (int)(e & (H_ - 1));
    float v = W[e];
    bf16 hi = __float2bfloat16_rn(v);
    bf16 lo = __float2bfloat16_rn(v - __bfloat162float(hi));
    wth[(long)c * H_ + o] = hi;
    wtl[(long)c * H_ + o] = lo;
}

// ---------------- HMMA split-bf16 GEMM, 2-CTA/SM config ---------------------
// C[m][n] = sum_k A[m][k]*B[n][k];  acc += Ah*Bh + Ah*Bl + Al*Bh
// CTA tile 128x64, BK=32, 8 warps (warp tile 32x32), 3-stage cp.async,
// __launch_bounds__(256,2) -> two resident CTAs overlap each other's stalls.
#define PITCH     80                       // 32 bf16 (64B) + 16B pad
#define A_TILE_B  (128 * PITCH)            // 10240
#define B_TILE_B  (64 * PITCH)             // 5120
#define STAGE_B   (2 * A_TILE_B + 2 * B_TILE_B)   // 30720
#define NSTAGE    3
#define SMEM_BYTES (NSTAGE * STAGE_B)      // 92160

__global__ __launch_bounds__(256, 2)
void gemm_mma(const bf16* __restrict__ Ah, const bf16* __restrict__ Al,
              const bf16* __restrict__ Bh, const bf16* __restrict__ Bl,
              float* __restrict__ Cf, bf16* __restrict__ Ch, bf16* __restrict__ Cl,
              int K, int lda, int ldb, int ldc,
              long sA, long sB, long sC, int split_out, int tri) {
    extern __shared__ char sm[];
    const uint32_t sb = smem_u32(sm);

    const int tid  = threadIdx.x;
    const int wid  = tid >> 5;
    const int lane = tid & 31;
    const int bz   = blockIdx.z;

    long m0, n0, cofs;
    int i0, i1;
    if (tri) {
        int t  = blockIdx.x >> 1;
        int ks = blockIdx.x & 1;
        m0 = (long)TI_LUT[t] * 128;
        n0 = (long)TJ_LUT[t] * 64;
        i0 = ks * ((K >> 1) >> 5);
        i1 = i0 + ((K >> 1) >> 5);
        cofs = (long)(bz * 2 + ks) * sC;
    } else {
        m0 = (long)blockIdx.y * 128;
        n0 = (long)blockIdx.x * 64;
        i0 = 0;
        i1 = K >> 5;
        cofs = (long)bz * sC;
    }

    const int warp_m = (wid >> 1) * 32;    // 4 m-groups
    const int warp_n = (wid & 1) * 32;     // 2 n-groups

    const bf16* gbase[4];
    gbase[0] = Ah + bz * sA + m0 * lda;
    gbase[1] = Al + bz * sA + m0 * lda;
    gbase[2] = Bh + bz * sB + n0 * ldb;
    gbase[3] = Bl + bz * sB + n0 * ldb;

    const uint32_t tbase[4] = {0, A_TILE_B, 2 * A_TILE_B, 2 * A_TILE_B + B_TILE_B};

    // per-thread cp.async mapping: 6 chunks of 16B (1536 total per stage)
    long c_goff[6];
    uint32_t c_soff[6];
    int c_tile[6];
#pragma unroll
    for (int i = 0; i < 6; i++) {
        int t = tid + i * 256;
        int tile, row, ci;
        if (t < 1024) { tile = t >> 9;           row = (t >> 2) & 127; ci = t & 3; }
        else          { int u = t - 1024; tile = 2 + (u >> 8); row = (u >> 2) & 63; ci = u & 3; }
        int ld = (tile < 2) ? lda : ldb;
        c_tile[i] = tile;
        c_goff[i] = (long)row * ld + ci * 8;
        c_soff[i] = tbase[tile] + (uint32_t)(row * PITCH + ci * 16);
    }

    auto load_stage = [&](int it) {
        int st = it % NSTAGE;
        long k0 = (long)it * 32;
        uint32_t sbase = sb + st * STAGE_B;
#pragma unroll
        for (int i = 0; i < 6; i++)
            cp16(sbase + c_soff[i], gbase[c_tile[i]] + k0 + c_goff[i]);
        cp_commit();
    };

    float acc[2][4][4];
#pragma unroll
    for (int mt = 0; mt < 2; mt++)
#pragma unroll
        for (int j = 0; j < 4; j++)
#pragma unroll
            for (int q = 0; q < 4; q++) acc[mt][j][q] = 0.f;

    load_stage(i0);
    load_stage(i0 + 1);

    const int a_rowoff = (lane & 7) + ((lane >> 3) & 1) * 8;
    const int a_choff  = (lane >> 4);
    const int b_rowoff = ((lane >> 4) & 1) * 8 + (lane & 7);
    const int b_choff  = ((lane >> 3) & 1);

    for (int it = i0; it < i1; it++) {
        cp_wait1();
        __syncthreads();
        if (it + 2 < i1) load_stage(it + 2);

        uint32_t sbase = sb + (it % NSTAGE) * STAGE_B;
        uint32_t sAh = sbase;
        uint32_t sAl = sbase + A_TILE_B;
        uint32_t sBh = sbase + 2 * A_TILE_B;
        uint32_t sBl = sbase + 2 * A_TILE_B + B_TILE_B;

#pragma unroll
        for (int ks = 0; ks < 2; ks++) {
            const int kc = ks * 2;
            uint32_t ah[2][4], al[2][4], bh[2][4], bl[2][4];
#pragma unroll
            for (int mt = 0; mt < 2; mt++) {
                uint32_t off = (uint32_t)((warp_m + mt * 16 + a_rowoff) * PITCH
                                          + (kc + a_choff) * 16);
                ldsm4(ah[mt], sAh + off);
                ldsm4(al[mt], sAl + off);
            }
#pragma unroll
            for (int jp = 0; jp < 2; jp++) {
                uint32_t off = (uint32_t)((warp_n + jp * 16 + b_rowoff) * PITCH
                                          + (kc + b_choff) * 16);
                ldsm4(bh[jp], sBh + off);
                ldsm4(bl[jp], sBl + off);
            }
#pragma unroll
            for (int p = 0; p < 3; p++) {
#pragma unroll
                for (int jp = 0; jp < 2; jp++) {
#pragma unroll
                    for (int mt = 0; mt < 2; mt++) {
                        const uint32_t* av = (p == 2) ? al[mt] : ah[mt];
                        const uint32_t* bv = (p == 1) ? bl[jp] : bh[jp];
                        mma16816(acc[mt][2 * jp],     av, bv);
                        mma16816(acc[mt][2 * jp + 1], av, bv + 2);
                    }
                }
            }
        }
    }

    // ---------------- epilogue ----------------
    const int r_lo = lane >> 2;
    const int c_lo = 2 * (lane & 3);
#pragma unroll
    for (int mt = 0; mt < 2; mt++) {
#pragma unroll
        for (int j = 0; j < 4; j++) {
            long row = m0 + warp_m + mt * 16 + r_lo;
            long col = n0 + warp_n + j * 8 + c_lo;
            float v0 = acc[mt][j][0], v1 = acc[mt][j][1];
            float v2 = acc[mt][j][2], v3 = acc[mt][j][3];
            if (!split_out) {
                float* p = Cf + cofs;
                *(float2*)(p + row * ldc + col)       = make_float2(v0, v1);
                *(float2*)(p + (row + 8) * ldc + col) = make_float2(v2, v3);
            } else {
                bf16 h0 = __float2bfloat16_rn(v0);
                bf16 h1 = __float2bfloat16_rn(v1);
                bf16 h2 = __float2bfloat16_rn(v2);
                bf16 h3 = __float2bfloat16_rn(v3);
                bf16 l0 = __float2bfloat16_rn(v0 - __bfloat162float(h0));
                bf16 l1 = __float2bfloat16_rn(v1 - __bfloat162float(h1));
                bf16 l2 = __float2bfloat16_rn(v2 - __bfloat162float(h2));
                bf16 l3 = __float2bfloat16_rn(v3 - __bfloat162float(h3));
                long o0 = cofs + row * ldc + col;
                long o1 = cofs + (row + 8) * ldc + col;
                *(__nv_bfloat162*)(Ch + o0) = __nv_bfloat162(h0, h1);
                *(__nv_bfloat162*)(Ch + o1) = __nv_bfloat162(h2, h3);
                *(__nv_bfloat162*)(Cl + o0) = __nv_bfloat162(l0, l1);
                *(__nv_bfloat162*)(Cl + o1) = __nv_bfloat162(l2, l3);
            }
        }
    }
}

// ---------------- G fixup: sum split-K partials, hi/lo split, mirror --------
// grid (72, 4, B_): tile t, 32-row chunk, batch. 256 threads.
// Mirror writes are benign overlaps: v(m,n) and v(n,m) are bitwise identical
// (same products, same accumulation order).
__global__ void g_fixup(const float* __restrict__ Gp,
                        bf16* __restrict__ Gh, bf16* __restrict__ Gl) {
    __shared__ bf16 shi[32][66];
    __shared__ bf16 slo[32][66];
    const int t = blockIdx.x, b = blockIdx.z;
    const long m0 = (long)TI_LUT[t] * 128 + blockIdx.y * 32;
    const long n0 = (long)TJ_LUT[t] * 64;
    const long HH = (long)H_ * H_;
    const float* P0 = Gp + (long)(b * 2 + 0) * HH;
    const float* P1 = Gp + (long)(b * 2 + 1) * HH;
    bf16* gh = Gh + (long)b * HH;
    bf16* gl = Gl + (long)b * HH;

    const int tid  = threadIdx.x;
    const int r    = tid >> 3;             // 0..31
    const int quad = tid & 7;              // 8 cols each

#pragma unroll
    for (int v4 = 0; v4 < 2; v4++) {
        int col = quad * 8 + v4 * 4;
        long off = (m0 + r) * H_ + n0 + col;
        float4 p0 = *(const float4*)(P0 + off);
        float4 p1 = *(const float4*)(P1 + off);
        float v[4] = {p0.x + p1.x, p0.y + p1.y, p0.z + p1.z, p0.w + p1.w};
        bf16 hi[4], lo[4];
#pragma unroll
        for (int q = 0; q < 4; q++) {
            hi[q] = __float2bfloat16_rn(v[q]);
            lo[q] = __float2bfloat16_rn(v[q] - __bfloat162float(hi[q]));
            shi[r][col + q] = hi[q];
            slo[r][col + q] = lo[q];
        }
        *(__nv_bfloat162*)(gh + off)     = __nv_bfloat162(hi[0], hi[1]);
        *(__nv_bfloat162*)(gh + off + 2) = __nv_bfloat162(hi[2], hi[3]);
        *(__nv_bfloat162*)(gl + off)     = __nv_bfloat162(lo[0], lo[1]);
        *(__nv_bfloat162*)(gl + off + 2) = __nv_bfloat162(lo[2], lo[3]);
    }
    __syncthreads();

    // mirror: write G[n0+cc][m0 + 0..31]
    const int cc   = tid >> 2;             // 0..63
    const int part = tid & 3;              // 8 rows each
    long moff = (n0 + cc) * H_ + m0;
#pragma unroll
    for (int k = 0; k < 4; k++) {
        int rr = part * 8 + 2 * k;
        *(__nv_bfloat162*)(gh + moff + rr) = __nv_bfloat162(shi[rr][cc], shi[rr + 1][cc]);
        *(__nv_bfloat162*)(gl + moff + rr) = __nv_bfloat162(slo[rr][cc], slo[rr + 1][cc]);
    }
}

// ---------------- launch ----------------------------------------------------
extern "C" void kernel_launch(void* const* d_in, const int* in_sizes, int n_in,
                              void* d_out, int out_size) {
    const float* x  = (const float*)d_in[0];
    const float* W  = (const float*)d_in[1];
    const float* cs = (const float*)d_in[2];
    const float* sn = (const float*)d_in[3];
    float* out = (float*)d_out;

    void *p0, *p1, *p2, *p3, *p4, *p5, *p6, *p7, *p8, *p9, *pGp;
    cudaGetSymbolAddress(&p0, g_h_hi);  cudaGetSymbolAddress(&p1, g_h_lo);
    cudaGetSymbolAddress(&p2, g_hT_hi); cudaGetSymbolAddress(&p3, g_hT_lo);
    cudaGetSymbolAddress(&p4, g_WT_hi); cudaGetSymbolAddress(&p5, g_WT_lo);
    cudaGetSymbolAddress(&p6, g_G_hi);  cudaGetSymbolAddress(&p7, g_G_lo);
    cudaGetSymbolAddress(&p8, g_MT_hi); cudaGetSymbolAddress(&p9, g_MT_lo);
    cudaGetSymbolAddress(&pGp, g_Gp);
    bf16 *hh = (bf16*)p0, *hl = (bf16*)p1, *hth = (bf16*)p2, *htl = (bf16*)p3;
    bf16 *wth = (bf16*)p4, *wtl = (bf16*)p5, *Gh = (bf16*)p6, *Gl = (bf16*)p7;
    bf16 *MTh = (bf16*)p8, *MTl = (bf16*)p9;
    float* Gp = (float*)pGp;

    cudaFuncSetAttribute(gemm_mma, cudaFuncAttributeMaxDynamicSharedMemorySize,
                         SMEM_BYTES);

    const long HL = (long)H_ * L_;
    const long HH = (long)H_ * H_;

    // 1) fused RoPE + split + transpose
    rope_split_t<<<dim3(L_ / 64, H_ / 64, B_), dim3(32, 8)>>>(
        x, cs, sn, hh, hl, hth, htl);

    // 2) W split + transpose
    wsplit_t<<<(H_ * H_) / 256, 256>>>(W, wth, wtl);

    // 3) G partials: 72 upper tiles (128x64), split-K=2 -> 288 CTAs (~1 wave)
    gemm_mma<<<dim3(144, 1, B_), 256, SMEM_BYTES>>>(
        hth, htl, hth, htl, Gp, nullptr, nullptr, L_, L_, L_, H_, HL, HL, HH, 0, 1);

    // 4) fixup: sum partials, split hi/lo, mirror to lower triangle
    g_fixup<<<dim3(72, 4, B_), 256>>>(Gp, Gh, Gl);

    // 5) M^T = G W : [H x H], K=H -> MT (bf16 split)
    gemm_mma<<<dim3(H_ / 64, H_ / 128, B_), 256, SMEM_BYTES>>>(
        Gh, Gl, wth, wtl, nullptr, MTh, MTl, H_, H_, H_, H_, HH, 0, HH, 1, 0);

    // 6) out = h M : [L x H], K=H -> fp32 out
    gemm_mma<<<dim3(H_ / 64, L_ / 128, B_), 256, SMEM_BYTES>>>(
        hh, hl, MTh, MTl, out, nullptr, nullptr, H_, H_, H_, H_, HL, HH, HL, 0, 0);
}

// round 10
// speedup vs baseline: 1.1301x; 1.1301x over previous
#include <cuda_runtime.h>
#include <cuda_bf16.h>
#include <cstdint>

#define B_ 2
#define L_ 4096
#define H_ 1024

typedef __nv_bfloat16 bf16;

// ---------------- scratch (__device__ globals; no runtime alloc) ------------
__device__ bf16  g_h_hi [B_ * L_ * H_];   // RoPE'd h, bf16 hi   [B][L][H]
__device__ bf16  g_h_lo [B_ * L_ * H_];   // residual lo
__device__ bf16  g_hT_hi[B_ * H_ * L_];   // h transposed        [B][H][L]
__device__ bf16  g_hT_lo[B_ * H_ * L_];
__device__ bf16  g_WT_hi[H_ * H_];        // W^T (rows = cols of W)
__device__ bf16  g_WT_lo[H_ * H_];
__device__ bf16  g_G_hi [B_ * H_ * H_];   // G = h^T h (symmetric)
__device__ bf16  g_G_lo [B_ * H_ * H_];
__device__ bf16  g_MT_hi[B_ * H_ * H_];   // M^T = G W
__device__ bf16  g_MT_lo[B_ * H_ * H_];
__device__ float g_Gp  [B_ * 2 * H_ * H_]; // split-K partials for G (fp32)

// upper-triangle tile LUT for 8x8 tile grid (36 unique 128x128 tiles)
__device__ const int TI_LUT[36] = {0,0,0,0,0,0,0,0, 1,1,1,1,1,1,1, 2,2,2,2,2,2,
                                   3,3,3,3,3, 4,4,4,4, 5,5,5, 6,6, 7};
__device__ const int TJ_LUT[36] = {0,1,2,3,4,5,6,7, 1,2,3,4,5,6,7, 2,3,4,5,6,7,
                                   3,4,5,6,7, 4,5,6,7, 5,6,7, 6,7, 7};

// ---------------- helpers ---------------------------------------------------
__device__ __forceinline__ uint32_t smem_u32(const void* p) {
    uint32_t a;
    asm("{ .reg .u64 t; cvta.to.shared.u64 t, %1; cvt.u32.u64 %0, t; }" : "=r"(a) : "l"(p));
    return a;
}
__device__ __forceinline__ void cp16(uint32_t saddr, const void* gaddr) {
    asm volatile("cp.async.cg.shared.global [%0], [%1], 16;" :: "r"(saddr), "l"(gaddr));
}
__device__ __forceinline__ void cp_commit() {
    asm volatile("cp.async.commit_group;" ::: "memory");
}
__device__ __forceinline__ void cp_wait1() {
    asm volatile("cp.async.wait_group 1;" ::: "memory");
}
__device__ __forceinline__ void ldsm4(uint32_t* r, uint32_t addr) {
    asm volatile("ldmatrix.sync.aligned.m8n8.x4.shared.b16 {%0,%1,%2,%3}, [%4];"
                 : "=r"(r[0]), "=r"(r[1]), "=r"(r[2]), "=r"(r[3]) : "r"(addr));
}
__device__ __forceinline__ void mma16816(float* c, const uint32_t* a, const uint32_t* b) {
    asm volatile(
        "mma.sync.aligned.m16n8k16.row.col.f32.bf16.bf16.f32 "
        "{%0,%1,%2,%3}, {%4,%5,%6,%7}, {%8,%9}, {%0,%1,%2,%3};"
        : "+f"(c[0]), "+f"(c[1]), "+f"(c[2]), "+f"(c[3])
        : "r"(a[0]), "r"(a[1]), "r"(a[2]), "r"(a[3]), "r"(b[0]), "r"(b[1]));
}

// ---------------- fused RoPE + split + transpose, pair-dedup ----------------
// cos[l, c+512] == cos[l, c] (tables are concat(freqs, freqs)), and column
// pair (c, c+512) shares the same x reads:
//   out[c]     = x[c]*cos - x[c+512]*sin
//   out[c+512] = x[c+512]*cos + x[c]*sin
// Each block: 64 l-rows x two 64-col blocks (h0 in [0,512), h1 = h0+512).
// Reads x once, cos/sin first half only. Writes hh/hl and hth/htl.
__global__ void rope_split_t(const float* __restrict__ x,
                             const float* __restrict__ cs,
                             const float* __restrict__ sn,
                             bf16* __restrict__ hh, bf16* __restrict__ hl,
                             bf16* __restrict__ hth, bf16* __restrict__ htl) {
    __shared__ bf16 tahi[64][66], talo[64][66];   // h0 block
    __shared__ bf16 tbhi[64][66], tblo[64][66];   // h1 block
    const int b  = blockIdx.z;
    const int l0 = blockIdx.x * 64;
    const int h0 = blockIdx.y * 64;          // in [0, 512)
    const int h1 = h0 + H_ / 2;
    const int tx = threadIdx.x, ty = threadIdx.y;  // 32 x 8
    const long base = (long)b * L_ * H_;
    const int c = 2 * tx;

#pragma unroll
    for (int i = 0; i < 8; i++) {
        int r = ty + 8 * i;
        long l = l0 + r;
        float2 xa = *(const float2*)(x + base + l * H_ + h0 + c);
        float2 xb = *(const float2*)(x + base + l * H_ + h1 + c);
        float2 cv = *(const float2*)(cs + l * H_ + h0 + c);
        float2 sv = *(const float2*)(sn + l * H_ + h0 + c);
        float oa0 = xa.x * cv.x - xb.x * sv.x;
        float oa1 = xa.y * cv.y - xb.y * sv.y;
        float ob0 = xb.x * cv.x + xa.x * sv.x;
        float ob1 = xb.y * cv.y + xa.y * sv.y;

        bf16 ahi0 = __float2bfloat16_rn(oa0), ahi1 = __float2bfloat16_rn(oa1);
        bf16 alo0 = __float2bfloat16_rn(oa0 - __bfloat162float(ahi0));
        bf16 alo1 = __float2bfloat16_rn(oa1 - __bfloat162float(ahi1));
        bf16 bhi0 = __float2bfloat16_rn(ob0), bhi1 = __float2bfloat16_rn(ob1);
        bf16 blo0 = __float2bfloat16_rn(ob0 - __bfloat162float(bhi0));
        bf16 blo1 = __float2bfloat16_rn(ob1 - __bfloat162float(bhi1));

        *(__nv_bfloat162*)(hh + base + l * H_ + h0 + c) = __nv_bfloat162(ahi0, ahi1);
        *(__nv_bfloat162*)(hl + base + l * H_ + h0 + c) = __nv_bfloat162(alo0, alo1);
        *(__nv_bfloat162*)(hh + base + l * H_ + h1 + c) = __nv_bfloat162(bhi0, bhi1);
        *(__nv_bfloat162*)(hl + base + l * H_ + h1 + c) = __nv_bfloat162(blo0, blo1);

        tahi[r][c] = ahi0; tahi[r][c + 1] = ahi1;
        talo[r][c] = alo0; talo[r][c + 1] = alo1;
        tbhi[r][c] = bhi0; tbhi[r][c + 1] = bhi1;
        tblo[r][c] = blo0; tblo[r][c + 1] = blo1;
    }
    __syncthreads();
#pragma unroll
    for (int i = 0; i < 8; i++) {
        int r = ty + 8 * i;
        long rowa = h0 + r, rowb = h1 + r;
        *(__nv_bfloat162*)(hth + base + rowa * L_ + l0 + c) =
            __nv_bfloat162(tahi[c][r], tahi[c + 1][r]);
        *(__nv_bfloat162*)(htl + base + rowa * L_ + l0 + c) =
            __nv_bfloat162(talo[c][r], talo[c + 1][r]);
        *(__nv_bfloat162*)(hth + base + rowb * L_ + l0 + c) =
            __nv_bfloat162(tbhi[c][r], tbhi[c + 1][r]);
        *(__nv_bfloat162*)(htl + base + rowb * L_ + l0 + c) =
            __nv_bfloat162(tblo[c][r], tblo[c + 1][r]);
    }
}

// ---------------- W split + transpose --------------------------------------
__global__ void wsplit_t(const float* __restrict__ W, bf16* __restrict__ wth,
                         bf16* __restrict__ wtl) {
    long e = (long)blockIdx.x * blockDim.x + threadIdx.x;
    int o = (int)(e >> 10), c = (int)(e & (H_ - 1));
    float v = W[e];
    bf16 hi = __float2bfloat16_rn(v);
    bf16 lo = __float2bfloat16_rn(v - __bfloat162float(hi));
    wth[(long)c * H_ + o] = hi;
    wtl[(long)c * H_ + o] = lo;
}

// ---------------- HMMA split-bf16 GEMM (R8 core) ----------------------------
// C[m][n] = sum_k A[m][k]*B[n][k];  acc += Ah*Bh + Ah*Bl + Al*Bh
// CTA tile 128x128, BK=64, 16 warps (warp tile 32x32), 3-stage cp.async.
// tri=1: blockIdx.x encodes (uppertile t, k-half ks); fp32 partial out.
#define PITCH    144
#define TILE_B   (128 * PITCH)
#define STAGE_B  (4 * TILE_B)
#define NSTAGE   3
#define SMEM_BYTES (NSTAGE * STAGE_B)     // 221184 B

__global__ __launch_bounds__(512, 1)
void gemm_mma(const bf16* __restrict__ Ah, const bf16* __restrict__ Al,
              const bf16* __restrict__ Bh, const bf16* __restrict__ Bl,
              float* __restrict__ Cf, bf16* __restrict__ Ch, bf16* __restrict__ Cl,
              int K, int lda, int ldb, int ldc,
              long sA, long sB, long sC, int split_out, int tri) {
    extern __shared__ char sm[];
    const uint32_t sb = smem_u32(sm);

    const int tid  = threadIdx.x;
    const int wid  = tid >> 5;
    const int lane = tid & 31;
    const int bz   = blockIdx.z;

    long m0, n0, cofs;
    int i0, i1;
    if (tri) {
        int t  = blockIdx.x >> 1;
        int ks = blockIdx.x & 1;
        m0 = (long)TI_LUT[t] * 128;
        n0 = (long)TJ_LUT[t] * 128;
        int kh = K >> 1;
        i0 = (ks * kh) >> 6;
        i1 = i0 + (kh >> 6);
        cofs = (long)(bz * 2 + ks) * sC;
    } else {
        m0 = (long)blockIdx.y * 128;
        n0 = (long)blockIdx.x * 128;
        i0 = 0;
        i1 = K >> 6;
        cofs = (long)bz * sC;
    }

    const int warp_m = (wid >> 2) * 32;
    const int warp_n = (wid & 3) * 32;

    const bf16* gbase[4];
    gbase[0] = Ah + bz * sA + m0 * lda;
    gbase[1] = Al + bz * sA + m0 * lda;
    gbase[2] = Bh + bz * sB + n0 * ldb;
    gbase[3] = Bl + bz * sB + n0 * ldb;

    long c_goff[8];
    uint32_t c_soff[8];
    int c_tile[8];
#pragma unroll
    for (int i = 0; i < 8; i++) {
        int t = tid + i * 512;
        int tile = t >> 10;
        int row  = (t >> 3) & 127;
        int ci   = t & 7;
        int ld   = (tile < 2) ? lda : ldb;
        c_tile[i] = tile;
        c_goff[i] = (long)row * ld + ci * 8;
        c_soff[i] = (uint32_t)(tile * TILE_B + row * PITCH + ci * 16);
    }

    auto load_stage = [&](int it) {
        int st = it % NSTAGE;
        long k0 = (long)it * 64;
        uint32_t sbase = sb + st * STAGE_B;
#pragma unroll
        for (int i = 0; i < 8; i++)
            cp16(sbase + c_soff[i], gbase[c_tile[i]] + k0 + c_goff[i]);
        cp_commit();
    };

    float acc[2][4][4];
#pragma unroll
    for (int mt = 0; mt < 2; mt++)
#pragma unroll
        for (int j = 0; j < 4; j++)
#pragma unroll
            for (int q = 0; q < 4; q++) acc[mt][j][q] = 0.f;

    load_stage(i0);
    load_stage(i0 + 1);

    const int a_rowoff = (lane & 7) + ((lane >> 3) & 1) * 8;
    const int a_choff  = (lane >> 4);
    const int b_rowoff = ((lane >> 4) & 1) * 8 + (lane & 7);
    const int b_choff  = ((lane >> 3) & 1);

    for (int it = i0; it < i1; it++) {
        cp_wait1();
        __syncthreads();
        if (it + 2 < i1) load_stage(it + 2);

        uint32_t sbase = sb + (it % NSTAGE) * STAGE_B;
        uint32_t sAh = sbase;
        uint32_t sAl = sbase + TILE_B;
        uint32_t sBh = sbase + 2 * TILE_B;
        uint32_t sBl = sbase + 3 * TILE_B;

#pragma unroll
        for (int ks = 0; ks < 4; ks++) {
            const int kc = ks * 2;
            uint32_t ah[2][4], al[2][4], bh[2][4], bl[2][4];
#pragma unroll
            for (int mt = 0; mt < 2; mt++) {
                uint32_t off = (uint32_t)((warp_m + mt * 16 + a_rowoff) * PITCH
                                          + (kc + a_choff) * 16);
                ldsm4(ah[mt], sAh + off);
                ldsm4(al[mt], sAl + off);
            }
#pragma unroll
            for (int jp = 0; jp < 2; jp++) {
                uint32_t off = (uint32_t)((warp_n + jp * 16 + b_rowoff) * PITCH
                                          + (kc + b_choff) * 16);
                ldsm4(bh[jp], sBh + off);
                ldsm4(bl[jp], sBl + off);
            }
#pragma unroll
            for (int p = 0; p < 3; p++) {
#pragma unroll
                for (int jp = 0; jp < 2; jp++) {
#pragma unroll
                    for (int mt = 0; mt < 2; mt++) {
                        const uint32_t* av = (p == 2) ? al[mt] : ah[mt];
                        const uint32_t* bv = (p == 1) ? bl[jp] : bh[jp];
                        mma16816(acc[mt][2 * jp],     av, bv);
                        mma16816(acc[mt][2 * jp + 1], av, bv + 2);
                    }
                }
            }
        }
    }

    // ---------------- epilogue ----------------
    const int r_lo = lane >> 2;
    const int c_lo = 2 * (lane & 3);
#pragma unroll
    for (int mt = 0; mt < 2; mt++) {
#pragma unroll
        for (int j = 0; j < 4; j++) {
            long row = m0 + warp_m + mt * 16 + r_lo;
            long col = n0 + warp_n + j * 8 + c_lo;
            float v0 = acc[mt][j][0], v1 = acc[mt][j][1];
            float v2 = acc[mt][j][2], v3 = acc[mt][j][3];
            if (!split_out) {
                float* p = Cf + cofs;
                *(float2*)(p + row * ldc + col)       = make_float2(v0, v1);
                *(float2*)(p + (row + 8) * ldc + col) = make_float2(v2, v3);
            } else {
                bf16 h0 = __float2bfloat16_rn(v0);
                bf16 h1 = __float2bfloat16_rn(v1);
                bf16 h2 = __float2bfloat16_rn(v2);
                bf16 h3 = __float2bfloat16_rn(v3);
                bf16 l0 = __float2bfloat16_rn(v0 - __bfloat162float(h0));
                bf16 l1 = __float2bfloat16_rn(v1 - __bfloat162float(h1));
                bf16 l2 = __float2bfloat16_rn(v2 - __bfloat162float(h2));
                bf16 l3 = __float2bfloat16_rn(v3 - __bfloat162float(h3));
                long o0 = cofs + row * ldc + col;
                long o1 = cofs + (row + 8) * ldc + col;
                *(__nv_bfloat162*)(Ch + o0) = __nv_bfloat162(h0, h1);
                *(__nv_bfloat162*)(Ch + o1) = __nv_bfloat162(h2, h3);
                *(__nv_bfloat162*)(Cl + o0) = __nv_bfloat162(l0, l1);
                *(__nv_bfloat162*)(Cl + o1) = __nv_bfloat162(l2, l3);
            }
        }
    }
}

// ---------------- G fixup: sum split-K partials, hi/lo split, mirror --------
// grid (36, 4, B_): tile t, 32-row chunk, batch. 256 threads.
__global__ void g_fixup(const float* __restrict__ Gp,
                        bf16* __restrict__ Gh, bf16* __restrict__ Gl) {
    __shared__ bf16 shi[32][132];
    __shared__ bf16 slo[32][132];
    const int t = blockIdx.x, b = blockIdx.z;
    const int ti = TI_LUT[t], tj = TJ_LUT[t];
    const long m0 = (long)ti * 128 + blockIdx.y * 32;
    const long n0 = (long)tj * 128;
    const long HH = (long)H_ * H_;
    const float* P0 = Gp + (long)(b * 2 + 0) * HH;
    const float* P1 = Gp + (long)(b * 2 + 1) * HH;
    bf16* gh = Gh + (long)b * HH;
    bf16* gl = Gl + (long)b * HH;

    const int tid = threadIdx.x;
    const int r   = tid >> 3;              // 0..31
    const int cs  = (tid & 7) * 16;        // 16 cols each

#pragma unroll
    for (int v4 = 0; v4 < 4; v4++) {
        int col = cs + v4 * 4;
        long off = (m0 + r) * H_ + n0 + col;
        float4 p0 = *(const float4*)(P0 + off);
        float4 p1 = *(const float4*)(P1 + off);
        float v[4] = {p0.x + p1.x, p0.y + p1.y, p0.z + p1.z, p0.w + p1.w};
        bf16 hi[4], lo[4];
#pragma unroll
        for (int q = 0; q < 4; q++) {
            hi[q] = __float2bfloat16_rn(v[q]);
            lo[q] = __float2bfloat16_rn(v[q] - __bfloat162float(hi[q]));
            shi[r][col + q] = hi[q];
            slo[r][col + q] = lo[q];
        }
        *(__nv_bfloat162*)(gh + off)     = __nv_bfloat162(hi[0], hi[1]);
        *(__nv_bfloat162*)(gh + off + 2) = __nv_bfloat162(hi[2], hi[3]);
        *(__nv_bfloat162*)(gl + off)     = __nv_bfloat162(lo[0], lo[1]);
        *(__nv_bfloat162*)(gl + off + 2) = __nv_bfloat162(lo[2], lo[3]);
    }

    if (ti == tj) return;   // diagonal tile: full square already written
    __syncthreads();

    const int cc   = tid >> 1;             // 0..127 (source column)
    const int half = tid & 1;              // 16 rows each
    long moff = (n0 + cc) * H_ + m0 + half * 16;
#pragma unroll
    for (int k = 0; k < 8; k++) {
        int rr = half * 16 + 2 * k;
        *(__nv_bfloat162*)(gh + moff + 2 * k) = __nv_bfloat162(shi[rr][cc], shi[rr + 1][cc]);
        *(__nv_bfloat162*)(gl + moff + 2 * k) = __nv_bfloat162(slo[rr][cc], slo[rr + 1][cc]);
    }
}

// ---------------- launch ----------------------------------------------------
extern "C" void kernel_launch(void* const* d_in, const int* in_sizes, int n_in,
                              void* d_out, int out_size) {
    const float* x  = (const float*)d_in[0];
    const float* W  = (const float*)d_in[1];
    const float* cs = (const float*)d_in[2];
    const float* sn = (const float*)d_in[3];
    float* out = (float*)d_out;

    void *p0, *p1, *p2, *p3, *p4, *p5, *p6, *p7, *p8, *p9, *pGp;
    cudaGetSymbolAddress(&p0, g_h_hi);  cudaGetSymbolAddress(&p1, g_h_lo);
    cudaGetSymbolAddress(&p2, g_hT_hi); cudaGetSymbolAddress(&p3, g_hT_lo);
    cudaGetSymbolAddress(&p4, g_WT_hi); cudaGetSymbolAddress(&p5, g_WT_lo);
    cudaGetSymbolAddress(&p6, g_G_hi);  cudaGetSymbolAddress(&p7, g_G_lo);
    cudaGetSymbolAddress(&p8, g_MT_hi); cudaGetSymbolAddress(&p9, g_MT_lo);
    cudaGetSymbolAddress(&pGp, g_Gp);
    bf16 *hh = (bf16*)p0, *hl = (bf16*)p1, *hth = (bf16*)p2, *htl = (bf16*)p3;
    bf16 *wth = (bf16*)p4, *wtl = (bf16*)p5, *Gh = (bf16*)p6, *Gl = (bf16*)p7;
    bf16 *MTh = (bf16*)p8, *MTl = (bf16*)p9;
    float* Gp = (float*)pGp;

    cudaFuncSetAttribute(gemm_mma, cudaFuncAttributeMaxDynamicSharedMemorySize,
                         SMEM_BYTES);

    const long HL = (long)H_ * L_;
    const long HH = (long)H_ * H_;

    // 1) fused RoPE + split + transpose (pair-dedup: minimal traffic)
    rope_split_t<<<dim3(L_ / 64, (H_ / 2) / 64, B_), dim3(32, 8)>>>(
        x, cs, sn, hh, hl, hth, htl);

    // 2) W split + transpose
    wsplit_t<<<(H_ * H_) / 256, 256>>>(W, wth, wtl);

    // 3) G partials: 36 upper tiles (128x128), split-K=2 -> 144 CTAs (1 wave)
    gemm_mma<<<dim3(72, 1, B_), 512, SMEM_BYTES>>>(
        hth, htl, hth, htl, Gp, nullptr, nullptr, L_, L_, L_, H_, HL, HL, HH, 0, 1);

    // 4) fixup: sum partials, split hi/lo, mirror lower triangle
    g_fixup<<<dim3(36, 4, B_), 256>>>(Gp, Gh, Gl);

    // 5) M^T = G W : [H x H], K=H -> MT (bf16 split)
    gemm_mma<<<dim3(H_ / 128, H_ / 128, B_), 512, SMEM_BYTES>>>(
        Gh, Gl, wth, wtl, nullptr, MTh, MTl, H_, H_, H_, H_, HH, 0, HH, 1, 0);

    // 6) out = h M : [L x H], K=H -> fp32 out
    gemm_mma<<<dim3(H_ / 128, L_ / 128, B_), 512, SMEM_BYTES>>>(
        hh, hl, MTh, MTl, out, nullptr, nullptr, H_, H_, H_, H_, HL, HH, HL, 0, 0);
}

// round 11
// speedup vs baseline: 1.1614x; 1.0277x over previous
#include <cuda_runtime.h>
#include <cuda_bf16.h>
#include <cstdint>

#define B_ 2
#define L_ 4096
#define H_ 1024

typedef __nv_bfloat16 bf16;

// ---------------- scratch (__device__ globals; no runtime alloc) ------------
__device__ bf16  g_h_hi [B_ * L_ * H_];
__device__ bf16  g_h_lo [B_ * L_ * H_];
__device__ bf16  g_hT_hi[B_ * H_ * L_];
__device__ bf16  g_hT_lo[B_ * H_ * L_];
__device__ bf16  g_WT_hi[H_ * H_];
__device__ bf16  g_WT_lo[H_ * H_];
__device__ bf16  g_G_hi [B_ * H_ * H_];
__device__ bf16  g_G_lo [B_ * H_ * H_];
__device__ bf16  g_MT_hi[B_ * H_ * H_];
__device__ bf16  g_MT_lo[B_ * H_ * H_];
__device__ float g_Gp  [B_ * 2 * H_ * H_];

// upper-triangle tile LUT for 8x8 tile grid (36 unique 128x128 tiles)
__device__ const int TI_LUT[36] = {0,0,0,0,0,0,0,0, 1,1,1,1,1,1,1, 2,2,2,2,2,2,
                                   3,3,3,3,3, 4,4,4,4, 5,5,5, 6,6, 7};
__device__ const int TJ_LUT[36] = {0,1,2,3,4,5,6,7, 1,2,3,4,5,6,7, 2,3,4,5,6,7,
                                   3,4,5,6,7, 4,5,6,7, 5,6,7, 6,7, 7};

// ---------------- helpers ---------------------------------------------------
__device__ __forceinline__ uint32_t smem_u32(const void* p) {
    uint32_t a;
    asm("{ .reg .u64 t; cvta.to.shared.u64 t, %1; cvt.u32.u64 %0, t; }" : "=r"(a) : "l"(p));
    return a;
}
__device__ __forceinline__ void cp16(uint32_t saddr, const void* gaddr) {
    asm volatile("cp.async.cg.shared.global [%0], [%1], 16;" :: "r"(saddr), "l"(gaddr));
}
__device__ __forceinline__ void cp_commit() {
    asm volatile("cp.async.commit_group;" ::: "memory");
}
__device__ __forceinline__ void cp_wait1() {
    asm volatile("cp.async.wait_group 1;" ::: "memory");
}
__device__ __forceinline__ void ldsm4(uint32_t* r, uint32_t addr) {
    asm volatile("ldmatrix.sync.aligned.m8n8.x4.shared.b16 {%0,%1,%2,%3}, [%4];"
                 : "=r"(r[0]), "=r"(r[1]), "=r"(r[2]), "=r"(r[3]) : "r"(addr));
}
__device__ __forceinline__ void mma16816(float* c, const uint32_t* a, const uint32_t* b) {
    asm volatile(
        "mma.sync.aligned.m16n8k16.row.col.f32.bf16.bf16.f32 "
        "{%0,%1,%2,%3}, {%4,%5,%6,%7}, {%8,%9}, {%0,%1,%2,%3};"
        : "+f"(c[0]), "+f"(c[1]), "+f"(c[2]), "+f"(c[3])
        : "r"(a[0]), "r"(a[1]), "r"(a[2]), "r"(a[3]), "r"(b[0]), "r"(b[1]));
}

// ---------------- fused RoPE + split + transpose, pair-dedup ----------------
__global__ void rope_split_t(const float* __restrict__ x,
                             const float* __restrict__ cs,
                             const float* __restrict__ sn,
                             bf16* __restrict__ hh, bf16* __restrict__ hl,
                             bf16* __restrict__ hth, bf16* __restrict__ htl) {
    __shared__ bf16 tahi[64][66], talo[64][66];
    __shared__ bf16 tbhi[64][66], tblo[64][66];
    const int b  = blockIdx.z;
    const int l0 = blockIdx.x * 64;
    const int h0 = blockIdx.y * 64;          // in [0, 512)
    const int h1 = h0 + H_ / 2;
    const int tx = threadIdx.x, ty = threadIdx.y;
    const long base = (long)b * L_ * H_;
    const int c = 2 * tx;

#pragma unroll
    for (int i = 0; i < 8; i++) {
        int r = ty + 8 * i;
        long l = l0 + r;
        float2 xa = *(const float2*)(x + base + l * H_ + h0 + c);
        float2 xb = *(const float2*)(x + base + l * H_ + h1 + c);
        float2 cv = *(const float2*)(cs + l * H_ + h0 + c);
        float2 sv = *(const float2*)(sn + l * H_ + h0 + c);
        float oa0 = xa.x * cv.x - xb.x * sv.x;
        float oa1 = xa.y * cv.y - xb.y * sv.y;
        float ob0 = xb.x * cv.x + xa.x * sv.x;
        float ob1 = xb.y * cv.y + xa.y * sv.y;

        bf16 ahi0 = __float2bfloat16_rn(oa0), ahi1 = __float2bfloat16_rn(oa1);
        bf16 alo0 = __float2bfloat16_rn(oa0 - __bfloat162float(ahi0));
        bf16 alo1 = __float2bfloat16_rn(oa1 - __bfloat162float(ahi1));
        bf16 bhi0 = __float2bfloat16_rn(ob0), bhi1 = __float2bfloat16_rn(ob1);
        bf16 blo0 = __float2bfloat16_rn(ob0 - __bfloat162float(bhi0));
        bf16 blo1 = __float2bfloat16_rn(ob1 - __bfloat162float(bhi1));

        *(__nv_bfloat162*)(hh + base + l * H_ + h0 + c) = __nv_bfloat162(ahi0, ahi1);
        *(__nv_bfloat162*)(hl + base + l * H_ + h0 + c) = __nv_bfloat162(alo0, alo1);
        *(__nv_bfloat162*)(hh + base + l * H_ + h1 + c) = __nv_bfloat162(bhi0, bhi1);
        *(__nv_bfloat162*)(hl + base + l * H_ + h1 + c) = __nv_bfloat162(blo0, blo1);

        tahi[r][c] = ahi0; tahi[r][c + 1] = ahi1;
        talo[r][c] = alo0; talo[r][c + 1] = alo1;
        tbhi[r][c] = bhi0; tbhi[r][c + 1] = bhi1;
        tblo[r][c] = blo0; tblo[r][c + 1] = blo1;
    }
    __syncthreads();
#pragma unroll
    for (int i = 0; i < 8; i++) {
        int r = ty + 8 * i;
        long rowa = h0 + r, rowb = h1 + r;
        *(__nv_bfloat162*)(hth + base + rowa * L_ + l0 + c) =
            __nv_bfloat162(tahi[c][r], tahi[c + 1][r]);
        *(__nv_bfloat162*)(htl + base + rowa * L_ + l0 + c) =
            __nv_bfloat162(talo[c][r], talo[c + 1][r]);
        *(__nv_bfloat162*)(hth + base + rowb * L_ + l0 + c) =
            __nv_bfloat162(tbhi[c][r], tbhi[c + 1][r]);
        *(__nv_bfloat162*)(htl + base + rowb * L_ + l0 + c) =
            __nv_bfloat162(tblo[c][r], tblo[c + 1][r]);
    }
}

// ---------------- W split + transpose --------------------------------------
__global__ void wsplit_t(const float* __restrict__ W, bf16* __restrict__ wth,
                         bf16* __restrict__ wtl) {
    long e = (long)blockIdx.x * blockDim.x + threadIdx.x;
    int o = (int)(e >> 10), c = (int)(e & (H_ - 1));
    float v = W[e];
    bf16 hi = __float2bfloat16_rn(v);
    bf16 lo = __float2bfloat16_rn(v - __bfloat162float(hi));
    wth[(long)c * H_ + o] = hi;
    wtl[(long)c * H_ + o] = lo;
}

// ---------------- HMMA split-bf16 GEMM (R8 core; used for G and M) ----------
#define PITCH    144
#define TILE_B   (128 * PITCH)
#define STAGE_B  (4 * TILE_B)
#define NSTAGE   3
#define SMEM_BYTES (NSTAGE * STAGE_B)     // 221184 B

__global__ __launch_bounds__(512, 1)
void gemm_mma(const bf16* __restrict__ Ah, const bf16* __restrict__ Al,
              const bf16* __restrict__ Bh, const bf16* __restrict__ Bl,
              float* __restrict__ Cf, bf16* __restrict__ Ch, bf16* __restrict__ Cl,
              int K, int lda, int ldb, int ldc,
              long sA, long sB, long sC, int split_out, int tri) {
    extern __shared__ char sm[];
    const uint32_t sb = smem_u32(sm);

    const int tid  = threadIdx.x;
    const int wid  = tid >> 5;
    const int lane = tid & 31;
    const int bz   = blockIdx.z;

    long m0, n0, cofs;
    int i0, i1;
    if (tri) {
        int t  = blockIdx.x >> 1;
        int ks = blockIdx.x & 1;
        m0 = (long)TI_LUT[t] * 128;
        n0 = (long)TJ_LUT[t] * 128;
        int kh = K >> 1;
        i0 = (ks * kh) >> 6;
        i1 = i0 + (kh >> 6);
        cofs = (long)(bz * 2 + ks) * sC;
    } else {
        m0 = (long)blockIdx.y * 128;
        n0 = (long)blockIdx.x * 128;
        i0 = 0;
        i1 = K >> 6;
        cofs = (long)bz * sC;
    }

    const int warp_m = (wid >> 2) * 32;
    const int warp_n = (wid & 3) * 32;

    const bf16* gbase[4];
    gbase[0] = Ah + bz * sA + m0 * lda;
    gbase[1] = Al + bz * sA + m0 * lda;
    gbase[2] = Bh + bz * sB + n0 * ldb;
    gbase[3] = Bl + bz * sB + n0 * ldb;

    long c_goff[8];
    uint32_t c_soff[8];
    int c_tile[8];
#pragma unroll
    for (int i = 0; i < 8; i++) {
        int t = tid + i * 512;
        int tile = t >> 10;
        int row  = (t >> 3) & 127;
        int ci   = t & 7;
        int ld   = (tile < 2) ? lda : ldb;
        c_tile[i] = tile;
        c_goff[i] = (long)row * ld + ci * 8;
        c_soff[i] = (uint32_t)(tile * TILE_B + row * PITCH + ci * 16);
    }

    auto load_stage = [&](int it) {
        int st = it % NSTAGE;
        long k0 = (long)it * 64;
        uint32_t sbase = sb + st * STAGE_B;
#pragma unroll
        for (int i = 0; i < 8; i++)
            cp16(sbase + c_soff[i], gbase[c_tile[i]] + k0 + c_goff[i]);
        cp_commit();
    };

    float acc[2][4][4];
#pragma unroll
    for (int mt = 0; mt < 2; mt++)
#pragma unroll
        for (int j = 0; j < 4; j++)
#pragma unroll
            for (int q = 0; q < 4; q++) acc[mt][j][q] = 0.f;

    load_stage(i0);
    load_stage(i0 + 1);

    const int a_rowoff = (lane & 7) + ((lane >> 3) & 1) * 8;
    const int a_choff  = (lane >> 4);
    const int b_rowoff = ((lane >> 4) & 1) * 8 + (lane & 7);
    const int b_choff  = ((lane >> 3) & 1);

    for (int it = i0; it < i1; it++) {
        cp_wait1();
        __syncthreads();
        if (it + 2 < i1) load_stage(it + 2);

        uint32_t sbase = sb + (it % NSTAGE) * STAGE_B;
        uint32_t sAh = sbase;
        uint32_t sAl = sbase + TILE_B;
        uint32_t sBh = sbase + 2 * TILE_B;
        uint32_t sBl = sbase + 3 * TILE_B;

#pragma unroll
        for (int ks = 0; ks < 4; ks++) {
            const int kc = ks * 2;
            uint32_t ah[2][4], al[2][4], bh[2][4], bl[2][4];
#pragma unroll
            for (int mt = 0; mt < 2; mt++) {
                uint32_t off = (uint32_t)((warp_m + mt * 16 + a_rowoff) * PITCH
                                          + (kc + a_choff) * 16);
                ldsm4(ah[mt], sAh + off);
                ldsm4(al[mt], sAl + off);
            }
#pragma unroll
            for (int jp = 0; jp < 2; jp++) {
                uint32_t off = (uint32_t)((warp_n + jp * 16 + b_rowoff) * PITCH
                                          + (kc + b_choff) * 16);
                ldsm4(bh[jp], sBh + off);
                ldsm4(bl[jp], sBl + off);
            }
#pragma unroll
            for (int p = 0; p < 3; p++) {
#pragma unroll
                for (int jp = 0; jp < 2; jp++) {
#pragma unroll
                    for (int mt = 0; mt < 2; mt++) {
                        const uint32_t* av = (p == 2) ? al[mt] : ah[mt];
                        const uint32_t* bv = (p == 1) ? bl[jp] : bh[jp];
                        mma16816(acc[mt][2 * jp],     av, bv);
                        mma16816(acc[mt][2 * jp + 1], av, bv + 2);
                    }
                }
            }
        }
    }

    const int r_lo = lane >> 2;
    const int c_lo = 2 * (lane & 3);
#pragma unroll
    for (int mt = 0; mt < 2; mt++) {
#pragma unroll
        for (int j = 0; j < 4; j++) {
            long row = m0 + warp_m + mt * 16 + r_lo;
            long col = n0 + warp_n + j * 8 + c_lo;
            float v0 = acc[mt][j][0], v1 = acc[mt][j][1];
            float v2 = acc[mt][j][2], v3 = acc[mt][j][3];
            if (!split_out) {
                float* p = Cf + cofs;
                *(float2*)(p + row * ldc + col)       = make_float2(v0, v1);
                *(float2*)(p + (row + 8) * ldc + col) = make_float2(v2, v3);
            } else {
                bf16 h0 = __float2bfloat16_rn(v0);
                bf16 h1 = __float2bfloat16_rn(v1);
                bf16 h2 = __float2bfloat16_rn(v2);
                bf16 h3 = __float2bfloat16_rn(v3);
                bf16 l0 = __float2bfloat16_rn(v0 - __bfloat162float(h0));
                bf16 l1 = __float2bfloat16_rn(v1 - __bfloat162float(h1));
                bf16 l2 = __float2bfloat16_rn(v2 - __bfloat162float(h2));
                bf16 l3 = __float2bfloat16_rn(v3 - __bfloat162float(h3));
                long o0 = cofs + row * ldc + col;
                long o1 = cofs + (row + 8) * ldc + col;
                *(__nv_bfloat162*)(Ch + o0) = __nv_bfloat162(h0, h1);
                *(__nv_bfloat162*)(Ch + o1) = __nv_bfloat162(h2, h3);
                *(__nv_bfloat162*)(Cl + o0) = __nv_bfloat162(l0, l1);
                *(__nv_bfloat162*)(Cl + o1) = __nv_bfloat162(l2, l3);
            }
        }
    }
}

// ---------------- wide HMMA GEMM: CTA 128x256, warp 64x64, fp32 out ---------
// Used for the out-GEMM. 8 warps (256 thr), BK=64, 2-stage cp.async.
// smem reads per MMA are ~2.2x lower than the 32x32-warp core.
#define WA_TILE   (128 * PITCH)            // 18432
#define WB_TILE   (256 * PITCH)            // 36864
#define WSTAGE_B  (2 * WA_TILE + 2 * WB_TILE)   // 110592
#define WSMEM_BYTES (2 * WSTAGE_B)         // 221184

__global__ __launch_bounds__(256, 1)
void gemm_wide(const bf16* __restrict__ Ah, const bf16* __restrict__ Al,
               const bf16* __restrict__ Bh, const bf16* __restrict__ Bl,
               float* __restrict__ Cf,
               int K, int lda, int ldb, int ldc,
               long sA, long sB, long sC) {
    extern __shared__ char sm[];
    const uint32_t sb = smem_u32(sm);

    const int tid  = threadIdx.x;
    const int wid  = tid >> 5;
    const int lane = tid & 31;
    const int bz   = blockIdx.z;
    const long m0  = (long)blockIdx.y * 128;
    const long n0  = (long)blockIdx.x * 256;

    const int warp_m = (wid >> 2) * 64;     // 2 m-groups
    const int warp_n = (wid & 3) * 64;      // 4 n-groups

    const bf16* gbase[4];
    gbase[0] = Ah + bz * sA + m0 * lda;
    gbase[1] = Al + bz * sA + m0 * lda;
    gbase[2] = Bh + bz * sB + n0 * ldb;
    gbase[3] = Bl + bz * sB + n0 * ldb;
    const uint32_t tb[4] = {0, WA_TILE, 2 * WA_TILE, 2 * WA_TILE + WB_TILE};

    // cp.async mapping: 6144 16B-chunks per stage, 24 per thread
    long c_goff[24];
    uint32_t c_soff[24];
    int c_tile[24];
#pragma unroll
    for (int i = 0; i < 24; i++) {
        int t = tid + i * 256;
        int tile, row, ci;
        if (t < 2048) { tile = t >> 10;           row = (t >> 3) & 127; ci = t & 7; }
        else          { int u = t - 2048; tile = 2 + (u >> 11); row = (u >> 3) & 255; ci = u & 7; }
        int ld = (tile < 2) ? lda : ldb;
        c_tile[i] = tile;
        c_goff[i] = (long)row * ld + ci * 8;
        c_soff[i] = tb[tile] + (uint32_t)(row * PITCH + ci * 16);
    }

    auto load_stage = [&](int it) {
        long k0 = (long)it * 64;
        uint32_t sbase = sb + (it & 1) * WSTAGE_B;
#pragma unroll
        for (int i = 0; i < 24; i++)
            cp16(sbase + c_soff[i], gbase[c_tile[i]] + k0 + c_goff[i]);
        cp_commit();
    };

    float acc[4][8][4];
#pragma unroll
    for (int mt = 0; mt < 4; mt++)
#pragma unroll
        for (int j = 0; j < 8; j++)
#pragma unroll
            for (int q = 0; q < 4; q++) acc[mt][j][q] = 0.f;

    const int nIter = K >> 6;
    load_stage(0);
    load_stage(1);

    const int a_rowoff = (lane & 7) + ((lane >> 3) & 1) * 8;
    const int a_choff  = (lane >> 4);
    const int b_rowoff = ((lane >> 4) & 1) * 8 + (lane & 7);
    const int b_choff  = ((lane >> 3) & 1);

    for (int it = 0; it < nIter; it++) {
        cp_wait1();
        __syncthreads();

        uint32_t sbase = sb + (it & 1) * WSTAGE_B;
        uint32_t sAh = sbase;
        uint32_t sAl = sbase + WA_TILE;
        uint32_t sBh = sbase + 2 * WA_TILE;
        uint32_t sBl = sbase + 2 * WA_TILE + WB_TILE;

#pragma unroll
        for (int ks = 0; ks < 4; ks++) {
            const int kc = ks * 2;
            uint32_t ah[4][4], al[4][4], bh[4][4], bl[4][4];
#pragma unroll
            for (int mt = 0; mt < 4; mt++) {
                uint32_t off = (uint32_t)((warp_m + mt * 16 + a_rowoff) * PITCH
                                          + (kc + a_choff) * 16);
                ldsm4(ah[mt], sAh + off);
                ldsm4(al[mt], sAl + off);
            }
#pragma unroll
            for (int jp = 0; jp < 4; jp++) {
                uint32_t off = (uint32_t)((warp_n + jp * 16 + b_rowoff) * PITCH
                                          + (kc + b_choff) * 16);
                ldsm4(bh[jp], sBh + off);
                ldsm4(bl[jp], sBl + off);
            }
            // 288 MMAs per slice; acc reuse spread 32 issues apart
#pragma unroll
            for (int p = 0; p < 3; p++) {
#pragma unroll
                for (int jp = 0; jp < 4; jp++) {
#pragma unroll
                    for (int mt = 0; mt < 4; mt++) {
                        const uint32_t* av = (p == 2) ? al[mt] : ah[mt];
                        const uint32_t* bv = (p == 1) ? bl[jp] : bh[jp];
                        mma16816(acc[mt][2 * jp],     av, bv);
                        mma16816(acc[mt][2 * jp + 1], av, bv + 2);
                    }
                }
            }
        }
        __syncthreads();
        if (it + 2 < nIter) load_stage(it + 2);
    }

    const int r_lo = lane >> 2;
    const int c_lo = 2 * (lane & 3);
    float* p = Cf + bz * sC;
#pragma unroll
    for (int mt = 0; mt < 4; mt++) {
#pragma unroll
        for (int j = 0; j < 8; j++) {
            long row = m0 + warp_m + mt * 16 + r_lo;
            long col = n0 + warp_n + j * 8 + c_lo;
            *(float2*)(p + row * ldc + col) =
                make_float2(acc[mt][j][0], acc[mt][j][1]);
            *(float2*)(p + (row + 8) * ldc + col) =
                make_float2(acc[mt][j][2], acc[mt][j][3]);
        }
    }
}

// ---------------- G fixup: sum split-K partials, hi/lo split, mirror --------
__global__ void g_fixup(const float* __restrict__ Gp,
                        bf16* __restrict__ Gh, bf16* __restrict__ Gl) {
    __shared__ bf16 shi[32][132];
    __shared__ bf16 slo[32][132];
    const int t = blockIdx.x, b = blockIdx.z;
    const int ti = TI_LUT[t], tj = TJ_LUT[t];
    const long m0 = (long)ti * 128 + blockIdx.y * 32;
    const long n0 = (long)tj * 128;
    const long HH = (long)H_ * H_;
    const float* P0 = Gp + (long)(b * 2 + 0) * HH;
    const float* P1 = Gp + (long)(b * 2 + 1) * HH;
    bf16* gh = Gh + (long)b * HH;
    bf16* gl = Gl + (long)b * HH;

    const int tid = threadIdx.x;
    const int r   = tid >> 3;
    const int cs  = (tid & 7) * 16;

#pragma unroll
    for (int v4 = 0; v4 < 4; v4++) {
        int col = cs + v4 * 4;
        long off = (m0 + r) * H_ + n0 + col;
        float4 p0 = *(const float4*)(P0 + off);
        float4 p1 = *(const float4*)(P1 + off);
        float v[4] = {p0.x + p1.x, p0.y + p1.y, p0.z + p1.z, p0.w + p1.w};
        bf16 hi[4], lo[4];
#pragma unroll
        for (int q = 0; q < 4; q++) {
            hi[q] = __float2bfloat16_rn(v[q]);
            lo[q] = __float2bfloat16_rn(v[q] - __bfloat162float(hi[q]));
            shi[r][col + q] = hi[q];
            slo[r][col + q] = lo[q];
        }
        *(__nv_bfloat162*)(gh + off)     = __nv_bfloat162(hi[0], hi[1]);
        *(__nv_bfloat162*)(gh + off + 2) = __nv_bfloat162(hi[2], hi[3]);
        *(__nv_bfloat162*)(gl + off)     = __nv_bfloat162(lo[0], lo[1]);
        *(__nv_bfloat162*)(gl + off + 2) = __nv_bfloat162(lo[2], lo[3]);
    }

    if (ti == tj) return;
    __syncthreads();

    const int cc   = tid >> 1;
    const int half = tid & 1;
    long moff = (n0 + cc) * H_ + m0 + half * 16;
#pragma unroll
    for (int k = 0; k < 8; k++) {
        int rr = half * 16 + 2 * k;
        *(__nv_bfloat162*)(gh + moff + 2 * k) = __nv_bfloat162(shi[rr][cc], shi[rr + 1][cc]);
        *(__nv_bfloat162*)(gl + moff + 2 * k) = __nv_bfloat162(slo[rr][cc], slo[rr + 1][cc]);
    }
}

// ---------------- launch ----------------------------------------------------
extern "C" void kernel_launch(void* const* d_in, const int* in_sizes, int n_in,
                              void* d_out, int out_size) {
    const float* x  = (const float*)d_in[0];
    const float* W  = (const float*)d_in[1];
    const float* cs = (const float*)d_in[2];
    const float* sn = (const float*)d_in[3];
    float* out = (float*)d_out;

    void *p0, *p1, *p2, *p3, *p4, *p5, *p6, *p7, *p8, *p9, *pGp;
    cudaGetSymbolAddress(&p0, g_h_hi);  cudaGetSymbolAddress(&p1, g_h_lo);
    cudaGetSymbolAddress(&p2, g_hT_hi); cudaGetSymbolAddress(&p3, g_hT_lo);
    cudaGetSymbolAddress(&p4, g_WT_hi); cudaGetSymbolAddress(&p5, g_WT_lo);
    cudaGetSymbolAddress(&p6, g_G_hi);  cudaGetSymbolAddress(&p7, g_G_lo);
    cudaGetSymbolAddress(&p8, g_MT_hi); cudaGetSymbolAddress(&p9, g_MT_lo);
    cudaGetSymbolAddress(&pGp, g_Gp);
    bf16 *hh = (bf16*)p0, *hl = (bf16*)p1, *hth = (bf16*)p2, *htl = (bf16*)p3;
    bf16 *wth = (bf16*)p4, *wtl = (bf16*)p5, *Gh = (bf16*)p6, *Gl = (bf16*)p7;
    bf16 *MTh = (bf16*)p8, *MTl = (bf16*)p9;
    float* Gp = (float*)pGp;

    cudaFuncSetAttribute(gemm_mma, cudaFuncAttributeMaxDynamicSharedMemorySize,
                         SMEM_BYTES);
    cudaFuncSetAttribute(gemm_wide, cudaFuncAttributeMaxDynamicSharedMemorySize,
                         WSMEM_BYTES);

    const long HL = (long)H_ * L_;
    const long HH = (long)H_ * H_;

    // 1) fused RoPE + split + transpose (pair-dedup)
    rope_split_t<<<dim3(L_ / 64, (H_ / 2) / 64, B_), dim3(32, 8)>>>(
        x, cs, sn, hh, hl, hth, htl);

    // 2) W split + transpose
    wsplit_t<<<(H_ * H_) / 256, 256>>>(W, wth, wtl);

    // 3) G partials: 36 upper tiles (128x128), split-K=2 -> 144 CTAs (1 wave)
    gemm_mma<<<dim3(72, 1, B_), 512, SMEM_BYTES>>>(
        hth, htl, hth, htl, Gp, nullptr, nullptr, L_, L_, L_, H_, HL, HL, HH, 0, 1);

    // 4) fixup: sum partials, split hi/lo, mirror lower triangle
    g_fixup<<<dim3(36, 4, B_), 256>>>(Gp, Gh, Gl);

    // 5) M^T = G W : [H x H], K=H -> MT (bf16 split)
    gemm_mma<<<dim3(H_ / 128, H_ / 128, B_), 512, SMEM_BYTES>>>(
        Gh, Gl, wth, wtl, nullptr, MTh, MTl, H_, H_, H_, H_, HH, 0, HH, 1, 0);

    // 6) out = h M : [L x H], K=H -> fp32 out (wide 128x256 kernel)
    gemm_wide<<<dim3(H_ / 256, L_ / 128, B_), 256, WSMEM_BYTES>>>(
        hh, hl, MTh, MTl, out, H_, H_, H_, H_, HL, HH, HL);
}